// round 2
// baseline (speedup 1.0000x reference)
#include <cuda_runtime.h>
#include <cstdint>

// Problem constants
#define BATCH 16
#define Hn 512
#define Wn 512
#define WPR 16      // 32-bit words per row (512/32)
#define ST 17       // smem row stride in words (bank-conflict padding)

// Bit-packed skeletons: [mask(0=pred,1=gt)][batch][row][word]  = 1 MB scratch
__device__ uint32_t g_skel[2][BATCH][Hn][WPR];
__device__ float g_metrics[BATCH][3];

// ---------------------------------------------------------------------------
// Kernel 1: binarize + Zhang-Suen skeletonize to convergence.
// One block per (batch, mask). 512 threads: thread t owns row t.
// Image held bit-packed in shared memory; sub-iterations computed into
// registers then written back (single buffer + syncthreads).
// ---------------------------------------------------------------------------
__global__ void __launch_bounds__(512) skel_kernel(const float* __restrict__ pred,
                                                   const float* __restrict__ gt) {
    __shared__ uint32_t buf[Hn * ST];
    __shared__ int s_changed;

    const int tid = threadIdx.x;
    const int b   = blockIdx.x & 15;
    const int m   = blockIdx.x >> 4;   // 0 = pred, 1 = gt
    const float* in = (m ? gt : pred) + (size_t)b * Hn * Wn;

    // --- binarize (coalesced: warp covers 32 consecutive columns of a row) ---
    const int wi = tid >> 5;           // warp id = word index
    for (int row = 0; row < Hn; ++row) {
        float v = in[row * Wn + tid];
        uint32_t bits = __ballot_sync(0xffffffffu, v > 0.5f);
        if ((tid & 31) == 0) buf[row * ST + wi] = bits;
    }
    if (tid == 0) s_changed = 0;
    __syncthreads();

    const int row = tid;
    const bool hasUp = (row > 0);
    const bool hasDn = (row < Hn - 1);
    const uint32_t* rU = &buf[(row - 1) * ST];
    const uint32_t* rC = &buf[row * ST];
    const uint32_t* rD = &buf[(row + 1) * ST];
    uint32_t* wC = &buf[row * ST];

    for (;;) {
        // two Zhang-Suen sub-iterations
        #pragma unroll 1
        for (int step = 0; step < 2; ++step) {
            uint32_t nw[WPR];
            uint32_t removed_any = 0;

            uint32_t aP = 0, cP = 0, bP = 0;
            uint32_t aC = hasUp ? rU[0] : 0u;
            uint32_t cC = rC[0];
            uint32_t bC = hasDn ? rD[0] : 0u;

            #pragma unroll
            for (int w = 0; w < WPR; ++w) {
                uint32_t aN = 0, cN = 0, bN = 0;
                if (w < WPR - 1) {
                    aN = hasUp ? rU[w + 1] : 0u;
                    cN = rC[w + 1];
                    bN = hasDn ? rD[w + 1] : 0u;
                }
                // neighbor bit-planes, P2..P9 clockwise from North
                uint32_t n0 = aC;                        // P2 N
                uint32_t n1 = (aC >> 1) | (aN << 31);    // P3 NE (col+1)
                uint32_t n2 = (cC >> 1) | (cN << 31);    // P4 E
                uint32_t n3 = (bC >> 1) | (bN << 31);    // P5 SE
                uint32_t n4 = bC;                        // P6 S
                uint32_t n5 = (bC << 1) | (bP >> 31);    // P7 SW (col-1)
                uint32_t n6 = (cC << 1) | (cP >> 31);    // P8 W
                uint32_t n7 = (aC << 1) | (aP >> 31);    // P9 NW

                // A == 1: exactly one 0->1 transition around the cycle
                uint32_t e0 = ~n0 & n1, e1 = ~n1 & n2, e2 = ~n2 & n3, e3 = ~n3 & n4;
                uint32_t e4 = ~n4 & n5, e5 = ~n5 & n6, e6 = ~n6 & n7, e7 = ~n7 & n0;
                uint32_t one = e0, more = 0;
                more |= one & e1; one |= e1;
                more |= one & e2; one |= e2;
                more |= one & e3; one |= e3;
                more |= one & e4; one |= e4;
                more |= one & e5; one |= e5;
                more |= one & e6; one |= e6;
                more |= one & e7; one |= e7;
                uint32_t A1 = one & ~more;

                // Bn >= 2  (at least 2 neighbors set)
                uint32_t o2 = n0, m2 = 0;
                m2 |= o2 & n1; o2 |= n1;
                m2 |= o2 & n2; o2 |= n2;
                m2 |= o2 & n3; o2 |= n3;
                m2 |= o2 & n4; o2 |= n4;
                m2 |= o2 & n5; o2 |= n5;
                m2 |= o2 & n6; o2 |= n6;
                m2 |= o2 & n7; o2 |= n7;
                uint32_t ge2 = m2;

                // Bn <= 6  <=>  at least 2 neighbors ZERO
                uint32_t z;
                uint32_t oz = ~n0, mz = 0;
                z = ~n1; mz |= oz & z; oz |= z;
                z = ~n2; mz |= oz & z; oz |= z;
                z = ~n3; mz |= oz & z; oz |= z;
                z = ~n4; mz |= oz & z; oz |= z;
                z = ~n5; mz |= oz & z; oz |= z;
                z = ~n6; mz |= oz & z; oz |= z;
                z = ~n7; mz |= oz & z; oz |= z;
                uint32_t le6 = mz;

                uint32_t cond = A1 & ge2 & le6;
                if (step == 0)
                    cond &= ~(n0 & n2 & n4) & ~(n2 & n4 & n6);
                else
                    cond &= ~(n0 & n2 & n6) & ~(n0 & n4 & n6);

                removed_any |= cC & cond;
                nw[w] = cC & ~cond;

                aP = aC; aC = aN;
                cP = cC; cC = cN;
                bP = bC; bC = bN;
            }
            __syncthreads();   // all reads of old image done
            #pragma unroll
            for (int w = 0; w < WPR; ++w) wC[w] = nw[w];
            if (removed_any) s_changed = 1;
            __syncthreads();   // writes + flag visible
        }
        int changed = s_changed;
        __syncthreads();       // everyone read the flag before reset
        if (!changed) break;
        if (tid == 0) s_changed = 0;
        __syncthreads();
    }

    // write out bit-packed skeleton
    #pragma unroll
    for (int w = 0; w < WPR; ++w)
        g_skel[m][b][row][w] = buf[row * ST + w];
}

// ---------------------------------------------------------------------------
// Kernel 2: dilation (Euclidean disk radius 3) + TP/FP/FN counting + metrics.
// One block per batch, thread t owns row t.
// ---------------------------------------------------------------------------
__device__ __forceinline__ uint32_t hdil(const uint32_t* M, int r, int w, int rad) {
    if (r < 0 || r >= Hn) return 0u;
    uint32_t p = (w > 0)        ? M[r * WPR + w - 1] : 0u;
    uint32_t c =                  M[r * WPR + w];
    uint32_t n = (w < WPR - 1)  ? M[r * WPR + w + 1] : 0u;
    uint32_t v = c;
    #pragma unroll
    for (int k = 1; k <= 3; ++k) {
        if (k > rad) break;
        v |= (c >> k) | (n << (32 - k));
        v |= (c << k) | (p >> (32 - k));
    }
    return v;
}

__device__ __forceinline__ uint32_t dil3(const uint32_t* M, int r, int w) {
    // disk of squared radius 9: dy=0 -> |dx|<=3 ; |dy| in {1,2} -> |dx|<=2 ; |dy|=3 -> dx=0
    uint32_t v = hdil(M, r, w, 3);
    v |= hdil(M, r - 1, w, 2) | hdil(M, r + 1, w, 2);
    v |= hdil(M, r - 2, w, 2) | hdil(M, r + 2, w, 2);
    if (r - 3 >= 0) v |= M[(r - 3) * WPR + w];
    if (r + 3 < Hn) v |= M[(r + 3) * WPR + w];
    return v;
}

__global__ void __launch_bounds__(512) count_kernel() {
    const int b = blockIdx.x;
    const int r = threadIdx.x;
    const uint32_t* P = &g_skel[0][b][0][0];
    const uint32_t* G = &g_skel[1][b][0][0];

    int tp = 0, fp = 0, fn = 0;
    #pragma unroll
    for (int w = 0; w < WPR; ++w) {
        uint32_t dg = dil3(G, r, w);
        uint32_t dp = dil3(P, r, w);
        uint32_t pw = P[r * WPR + w];
        uint32_t gw = G[r * WPR + w];
        tp += __popc(pw & dg);
        fp += __popc(pw & ~dg);
        fn += __popc(gw & ~dp);
    }

    __shared__ int stp, sfp, sfn;
    if (r == 0) { stp = 0; sfp = 0; sfn = 0; }
    __syncthreads();
    #pragma unroll
    for (int o = 16; o > 0; o >>= 1) {
        tp += __shfl_down_sync(0xffffffffu, tp, o);
        fp += __shfl_down_sync(0xffffffffu, fp, o);
        fn += __shfl_down_sync(0xffffffffu, fn, o);
    }
    if ((r & 31) == 0) {
        atomicAdd(&stp, tp);
        atomicAdd(&sfp, fp);
        atomicAdd(&sfn, fn);
    }
    __syncthreads();
    if (r == 0) {
        float TP = (float)stp, FP = (float)sfp, FN = (float)sfn;
        g_metrics[b][0] = TP / (TP + FP + 1e-12f);        // correctness
        g_metrics[b][1] = TP / (TP + FN + 1e-12f);        // completeness
        g_metrics[b][2] = TP / (TP + FP + FN + 1e-12f);   // quality
    }
}

// ---------------------------------------------------------------------------
// Kernel 3: mean over batch, fixed summation order (deterministic).
// ---------------------------------------------------------------------------
__global__ void finalize_kernel(float* __restrict__ out) {
    int t = threadIdx.x;
    if (t < 3) {
        float s = 0.0f;
        for (int b = 0; b < BATCH; ++b) s += g_metrics[b][t];
        out[t] = s * (1.0f / 16.0f);
    }
}

extern "C" void kernel_launch(void* const* d_in, const int* in_sizes, int n_in,
                              void* d_out, int out_size) {
    (void)in_sizes; (void)n_in; (void)out_size;
    const float* pred = (const float*)d_in[0];
    const float* gt   = (const float*)d_in[1];
    skel_kernel<<<32, 512>>>(pred, gt);
    count_kernel<<<BATCH, 512>>>();
    finalize_kernel<<<1, 32>>>((float*)d_out);
}

// round 3
// speedup vs baseline: 2.0316x; 2.0316x over previous
#include <cuda_runtime.h>
#include <cstdint>

#define BATCH 16
#define Hn 512
#define Wn 512
#define WPR 16      // 32-bit words per row
#define ST 17       // smem row stride (bank padding)

__device__ uint32_t g_skel[2][BATCH][Hn][WPR];
__device__ int g_counts[BATCH][3];   // TP, FP, FN (integer -> deterministic)

// ---------------------------------------------------------------------------
// Kernel 1: binarize + Zhang-Suen skeletonize to convergence.
// One block per (batch, mask). 1024 threads: 2 threads per row, 8 words each.
// Dirty-row skipping via iteration-stamped per-row change flags.
// ---------------------------------------------------------------------------
__global__ void __launch_bounds__(1024) skel_kernel(const float* __restrict__ pred,
                                                    const float* __restrict__ gt) {
    __shared__ uint32_t buf[Hn * ST];
    __shared__ int s_chg[2][Hn];   // stamp of last sub-iteration this row changed
    __shared__ int s_changed;      // max stamp at which any removal happened

    const int tid = threadIdx.x;
    const int b   = blockIdx.x & 15;
    const int m   = blockIdx.x >> 4;   // 0 = pred, 1 = gt
    const float* in = (m ? gt : pred) + (size_t)b * Hn * Wn;

    // zero global counters for count_kernel (runs strictly after us)
    if (blockIdx.x == 0 && tid < BATCH * 3) (&g_counts[0][0])[tid] = 0;

    // --- binarize (coalesced, warp ballots -> bit-packed words) ---
    #pragma unroll 4
    for (int p = 0; p < (Hn * Wn) / 1024; ++p) {
        int idx = p * 1024 + tid;
        float v = in[idx];
        uint32_t bits = __ballot_sync(0xffffffffu, v > 0.5f);
        if ((tid & 31) == 0) {
            int row  = idx >> 9;
            int word = (idx >> 5) & 15;
            buf[row * ST + word] = bits;
        }
    }
    if (tid < Hn) { s_chg[0][tid] = 0; s_chg[1][tid] = 0; }
    if (tid == 0) s_changed = 0;
    __syncthreads();

    const int row   = tid >> 1;
    const int wh    = tid & 1;
    const int wbase = wh * 8;
    const bool hasUp = (row > 0);
    const bool hasDn = (row < Hn - 1);
    const uint32_t* rU = &buf[(row - 1) * ST];
    const uint32_t* rC = &buf[row * ST];
    const uint32_t* rD = &buf[(row + 1) * ST];
    uint32_t* wC = &buf[row * ST];

    int s = 0;  // global sub-iteration counter (uniform across threads)
    for (;;) {
        #pragma unroll 1
        for (int step = 0; step < 2; ++step) {
            ++s;
            // dirty iff row r-1..r+1 changed in the previous sub-iteration
            const int pb = (s - 1) & 1, ps = s - 1;
            bool dirty = (s_chg[pb][row] == ps);
            if (!dirty && hasUp) dirty = (s_chg[pb][row - 1] == ps);
            if (!dirty && hasDn) dirty = (s_chg[pb][row + 1] == ps);

            uint32_t nw[8];
            uint32_t removed = 0;
            if (dirty) {
                uint32_t aP = (wh && hasUp) ? rU[7] : 0u;
                uint32_t cP = wh ? rC[7] : 0u;
                uint32_t bP = (wh && hasDn) ? rD[7] : 0u;
                uint32_t aC = hasUp ? rU[wbase] : 0u;
                uint32_t cC = rC[wbase];
                uint32_t bC = hasDn ? rD[wbase] : 0u;

                #pragma unroll
                for (int w = 0; w < 8; ++w) {
                    const int gw = wbase + w;
                    uint32_t aN = 0, cN = 0, bN = 0;
                    if (gw < WPR - 1) {
                        aN = hasUp ? rU[gw + 1] : 0u;
                        cN = rC[gw + 1];
                        bN = hasDn ? rD[gw + 1] : 0u;
                    }
                    // P2..P9 clockwise from North
                    uint32_t n0 = aC;
                    uint32_t n1 = (aC >> 1) | (aN << 31);
                    uint32_t n2 = (cC >> 1) | (cN << 31);
                    uint32_t n3 = (bC >> 1) | (bN << 31);
                    uint32_t n4 = bC;
                    uint32_t n5 = (bC << 1) | (bP >> 31);
                    uint32_t n6 = (cC << 1) | (cP >> 31);
                    uint32_t n7 = (aC << 1) | (aP >> 31);

                    // A == 1 (exactly one 0->1 transition)
                    uint32_t e0 = ~n0 & n1, e1 = ~n1 & n2, e2 = ~n2 & n3, e3 = ~n3 & n4;
                    uint32_t e4 = ~n4 & n5, e5 = ~n5 & n6, e6 = ~n6 & n7, e7 = ~n7 & n0;
                    uint32_t one = e0, more = 0;
                    more |= one & e1; one |= e1;
                    more |= one & e2; one |= e2;
                    more |= one & e3; one |= e3;
                    more |= one & e4; one |= e4;
                    more |= one & e5; one |= e5;
                    more |= one & e6; one |= e6;
                    more |= one & e7; one |= e7;
                    uint32_t A1 = one & ~more;

                    // Bn >= 2
                    uint32_t o2 = n0, m2 = 0;
                    m2 |= o2 & n1; o2 |= n1;
                    m2 |= o2 & n2; o2 |= n2;
                    m2 |= o2 & n3; o2 |= n3;
                    m2 |= o2 & n4; o2 |= n4;
                    m2 |= o2 & n5; o2 |= n5;
                    m2 |= o2 & n6; o2 |= n6;
                    m2 |= o2 & n7; o2 |= n7;
                    uint32_t ge2 = m2;

                    // Bn <= 6  (at least 2 neighbors zero)
                    uint32_t z, oz = ~n0, mz = 0;
                    z = ~n1; mz |= oz & z; oz |= z;
                    z = ~n2; mz |= oz & z; oz |= z;
                    z = ~n3; mz |= oz & z; oz |= z;
                    z = ~n4; mz |= oz & z; oz |= z;
                    z = ~n5; mz |= oz & z; oz |= z;
                    z = ~n6; mz |= oz & z; oz |= z;
                    z = ~n7; mz |= oz & z; oz |= z;
                    uint32_t le6 = mz;

                    uint32_t cond = A1 & ge2 & le6;
                    if (step == 0)
                        cond &= ~(n0 & n2 & n4) & ~(n2 & n4 & n6);
                    else
                        cond &= ~(n0 & n2 & n6) & ~(n0 & n4 & n6);

                    removed |= cC & cond;
                    nw[w] = cC & ~cond;

                    aP = aC; aC = aN;
                    cP = cC; cC = cN;
                    bP = bC; bC = bN;
                }
            }
            __syncthreads();   // all reads done
            if (dirty) {
                #pragma unroll
                for (int w = 0; w < 8; ++w) wC[wbase + w] = nw[w];
                if (removed) { s_chg[s & 1][row] = s; s_changed = s; }
            }
            __syncthreads();   // writes visible
        }
        if (s_changed <= s - 2) break;   // no removal in either sub-iteration
    }

    // write out bit-packed skeleton
    #pragma unroll
    for (int w = 0; w < 8; ++w)
        g_skel[m][b][row][wbase + w] = buf[row * ST + wbase + w];
}

// ---------------------------------------------------------------------------
// Kernel 2: dilation by Euclidean disk radius 3 + TP/FP/FN counting.
// Grid (batch, slab): 16 x 16 blocks, 512 threads; 32 rows + 3-row halo in smem.
// ---------------------------------------------------------------------------
#define SLAB 32
#define SROWS (SLAB + 6)

__device__ __forceinline__ uint32_t hdil3s(const uint32_t* M, int r, int w) {
    uint32_t p = (w > 0)       ? M[r * WPR + w - 1] : 0u;
    uint32_t c =                 M[r * WPR + w];
    uint32_t n = (w < WPR - 1) ? M[r * WPR + w + 1] : 0u;
    uint32_t v = c;
    v |= (c >> 1) | (n << 31); v |= (c << 1) | (p >> 31);
    v |= (c >> 2) | (n << 30); v |= (c << 2) | (p >> 30);
    v |= (c >> 3) | (n << 29); v |= (c << 3) | (p >> 29);
    return v;
}
__device__ __forceinline__ uint32_t hdil2s(const uint32_t* M, int r, int w) {
    uint32_t p = (w > 0)       ? M[r * WPR + w - 1] : 0u;
    uint32_t c =                 M[r * WPR + w];
    uint32_t n = (w < WPR - 1) ? M[r * WPR + w + 1] : 0u;
    uint32_t v = c;
    v |= (c >> 1) | (n << 31); v |= (c << 1) | (p >> 31);
    v |= (c >> 2) | (n << 30); v |= (c << 2) | (p >> 30);
    return v;
}
__device__ __forceinline__ uint32_t dil3s(const uint32_t* M, int r, int w) {
    // squared radius 9: dy=0 -> |dx|<=3; |dy| in {1,2} -> |dx|<=2; |dy|=3 -> dx=0
    uint32_t v = hdil3s(M, r, w);
    v |= hdil2s(M, r - 1, w) | hdil2s(M, r + 1, w);
    v |= hdil2s(M, r - 2, w) | hdil2s(M, r + 2, w);
    v |= M[(r - 3) * WPR + w] | M[(r + 3) * WPR + w];
    return v;
}

__global__ void __launch_bounds__(512) count_kernel() {
    const int b    = blockIdx.x;
    const int slab = blockIdx.y;
    __shared__ uint32_t sP[SROWS * WPR];
    __shared__ uint32_t sG[SROWS * WPR];

    const uint32_t* P = &g_skel[0][b][0][0];
    const uint32_t* G = &g_skel[1][b][0][0];
    const int tid = threadIdx.x;
    const int base = slab * SLAB - 3;

    for (int i = tid; i < SROWS * WPR; i += 512) {
        int rr = base + i / WPR;
        int w  = i % WPR;
        uint32_t pv = 0, gv = 0;
        if (rr >= 0 && rr < Hn) { pv = P[rr * WPR + w]; gv = G[rr * WPR + w]; }
        sP[i] = pv; sG[i] = gv;
    }
    __syncthreads();

    const int rl = tid / WPR + 3;   // local row 3..34
    const int w  = tid % WPR;
    uint32_t dg = dil3s(sG, rl, w);
    uint32_t dp = dil3s(sP, rl, w);
    uint32_t pw = sP[rl * WPR + w];
    uint32_t gw = sG[rl * WPR + w];
    int tp = __popc(pw & dg);
    int fp = __popc(pw & ~dg);
    int fn = __popc(gw & ~dp);

    __shared__ int stp, sfp, sfn;
    if (tid == 0) { stp = 0; sfp = 0; sfn = 0; }
    __syncthreads();
    #pragma unroll
    for (int o = 16; o > 0; o >>= 1) {
        tp += __shfl_down_sync(0xffffffffu, tp, o);
        fp += __shfl_down_sync(0xffffffffu, fp, o);
        fn += __shfl_down_sync(0xffffffffu, fn, o);
    }
    if ((tid & 31) == 0) {
        atomicAdd(&stp, tp);
        atomicAdd(&sfp, fp);
        atomicAdd(&sfn, fn);
    }
    __syncthreads();
    if (tid == 0) {
        atomicAdd(&g_counts[b][0], stp);
        atomicAdd(&g_counts[b][1], sfp);
        atomicAdd(&g_counts[b][2], sfn);
    }
}

// ---------------------------------------------------------------------------
// Kernel 3: metrics per batch + mean, fixed order (deterministic).
// ---------------------------------------------------------------------------
__global__ void finalize_kernel(float* __restrict__ out) {
    if (threadIdx.x == 0) {
        float s0 = 0.f, s1 = 0.f, s2 = 0.f;
        for (int b = 0; b < BATCH; ++b) {
            float TP = (float)g_counts[b][0];
            float FP = (float)g_counts[b][1];
            float FN = (float)g_counts[b][2];
            s0 += TP / (TP + FP + 1e-12f);
            s1 += TP / (TP + FN + 1e-12f);
            s2 += TP / (TP + FP + FN + 1e-12f);
        }
        out[0] = s0 * (1.0f / BATCH);
        out[1] = s1 * (1.0f / BATCH);
        out[2] = s2 * (1.0f / BATCH);
    }
}

extern "C" void kernel_launch(void* const* d_in, const int* in_sizes, int n_in,
                              void* d_out, int out_size) {
    (void)in_sizes; (void)n_in; (void)out_size;
    const float* pred = (const float*)d_in[0];
    const float* gt   = (const float*)d_in[1];
    skel_kernel<<<32, 1024>>>(pred, gt);
    count_kernel<<<dim3(BATCH, Hn / SLAB), 512>>>();
    finalize_kernel<<<1, 32>>>((float*)d_out);
}

// round 4
// speedup vs baseline: 2.2472x; 1.1061x over previous
#include <cuda_runtime.h>
#include <cstdint>

#define BATCH 16
#define Hn 512
#define Wn 512
#define WPR 16      // 32-bit words per row
#define ST 17       // smem row stride (bank padding)
#define BUFW (Hn * ST)

__device__ uint32_t g_skel[2][BATCH][Hn][WPR];
__device__ int g_counts[BATCH][3];   // TP, FP, FN (integer -> deterministic)
__device__ int g_ticket;
__device__ float* g_outp;            // stashed output pointer for fused finalize

// ---------------------------------------------------------------------------
// Kernel 1: binarize + Zhang-Suen skeletonize to convergence.
// One block per (batch, mask). 1024 threads: 2 per row, 8 words each, own row
// held in registers. Ping-pong smem buffers -> ONE __syncthreads per
// sub-iteration. Dirty-row skipping via iteration-stamped flags; per-thread
// skip-store for converged half-rows.
// ---------------------------------------------------------------------------
__global__ void __launch_bounds__(1024) skel_kernel(const float* __restrict__ pred,
                                                    const float* __restrict__ gt) {
    extern __shared__ uint32_t dyn[];          // 2 * BUFW words
    __shared__ int s_chg[2][Hn];               // stamp of last change, by parity
    __shared__ int s_changed;                  // max stamp with any removal

    const int tid = threadIdx.x;
    const int b   = blockIdx.x & 15;
    const int m   = blockIdx.x >> 4;           // 0 = pred, 1 = gt
    const float* in = (m ? gt : pred) + (size_t)b * Hn * Wn;

    // zero global counters + ticket (count kernel runs strictly after us)
    if (blockIdx.x == 0 && tid < BATCH * 3 + 1) {
        if (tid < BATCH * 3) (&g_counts[0][0])[tid] = 0;
        else g_ticket = 0;
    }

    // --- binarize into buf0 (coalesced, warp ballots -> packed words) ---
    uint32_t* buf0 = dyn;
    #pragma unroll 4
    for (int p = 0; p < (Hn * Wn) / 1024; ++p) {
        int idx = p * 1024 + tid;
        float v = in[idx];
        uint32_t bits = __ballot_sync(0xffffffffu, v > 0.5f);
        if ((tid & 31) == 0) {
            int row  = idx >> 9;
            int word = (idx >> 5) & 15;
            buf0[row * ST + word] = bits;
        }
    }
    if (tid < Hn) { s_chg[0][tid] = 0; s_chg[1][tid] = 0; }
    if (tid == 0) s_changed = 0;
    __syncthreads();

    const int row   = tid >> 1;
    const int wh    = tid & 1;
    const int wbase = wh * 8;
    const bool hasUp = (row > 0);
    const bool hasDn = (row < Hn - 1);

    // own 8 words live in registers
    uint32_t R[8];
    #pragma unroll
    for (int w = 0; w < 8; ++w) R[w] = buf0[row * ST + wbase + w];

    int s = 0;
    int myLast = 0;   // last sub-iteration where THIS thread removed a pixel

    for (;;) {
        ++s;
        uint32_t* cur = dyn + (s & 1) * BUFW;
        // store own words (skip if provably already correct in this parity buf)
        if (myLast > s - 3) {
            #pragma unroll
            for (int w = 0; w < 8; ++w) cur[row * ST + wbase + w] = R[w];
        }
        __syncthreads();

        // converged? (no removals in sub-iters s-1 and s-2)
        if (s_changed <= s - 3) break;

        // dirty iff any of rows r-1..r+1 changed in sub-iteration s-1
        const int pb = (s - 1) & 1, ps = s - 1;
        bool dirty = (s_chg[pb][row] == ps);
        if (!dirty && hasUp) dirty = (s_chg[pb][row - 1] == ps);
        if (!dirty && hasDn) dirty = (s_chg[pb][row + 1] == ps);
        if (!dirty) continue;

        const int step = (s - 1) & 1 ^ ((s - 1) & 1);  // placeholder, set below
        const int sub  = (s + 1) & 1;  // s odd -> sub-iter 0 ; s even -> sub-iter 1
        const uint32_t* rU = cur + (row - 1) * ST;
        const uint32_t* rD = cur + (row + 1) * ST;
        const uint32_t* rO = cur + row * ST;

        uint32_t aP = (wh && hasUp) ? rU[7] : 0u;
        uint32_t bP = (wh && hasDn) ? rD[7] : 0u;
        uint32_t cP = wh ? rO[7] : 0u;
        uint32_t aC = hasUp ? rU[wbase] : 0u;
        uint32_t bC = hasDn ? rD[wbase] : 0u;
        uint32_t cC = R[0];
        uint32_t cRight = (wh == 0) ? rO[8] : 0u;   // word past own half

        uint32_t removed = 0;
        uint32_t nR[8];
        #pragma unroll
        for (int w = 0; w < 8; ++w) {
            const int gw = wbase + w;
            uint32_t aN = 0, cN = 0, bN = 0;
            if (gw < WPR - 1) {
                aN = hasUp ? rU[gw + 1] : 0u;
                bN = hasDn ? rD[gw + 1] : 0u;
            }
            cN = (w < 7) ? R[w + 1] : cRight;

            // P2..P9 clockwise from North
            uint32_t n0 = aC;
            uint32_t n1 = (aC >> 1) | (aN << 31);
            uint32_t n2 = (cC >> 1) | (cN << 31);
            uint32_t n3 = (bC >> 1) | (bN << 31);
            uint32_t n4 = bC;
            uint32_t n5 = (bC << 1) | (bP >> 31);
            uint32_t n6 = (cC << 1) | (cP >> 31);
            uint32_t n7 = (aC << 1) | (aP >> 31);

            // A == 1 (exactly one 0->1 transition around the ring)
            uint32_t e0 = ~n0 & n1, e1 = ~n1 & n2, e2 = ~n2 & n3, e3 = ~n3 & n4;
            uint32_t e4 = ~n4 & n5, e5 = ~n5 & n6, e6 = ~n6 & n7, e7 = ~n7 & n0;
            uint32_t one = e0, more = 0;
            more |= one & e1; one |= e1;
            more |= one & e2; one |= e2;
            more |= one & e3; one |= e3;
            more |= one & e4; one |= e4;
            more |= one & e5; one |= e5;
            more |= one & e6; one |= e6;
            more |= one & e7; one |= e7;
            uint32_t A1 = one & ~more;

            // Bn >= 2
            uint32_t o2 = n0, m2 = 0;
            m2 |= o2 & n1; o2 |= n1;
            m2 |= o2 & n2; o2 |= n2;
            m2 |= o2 & n3; o2 |= n3;
            m2 |= o2 & n4; o2 |= n4;
            m2 |= o2 & n5; o2 |= n5;
            m2 |= o2 & n6; o2 |= n6;
            m2 |= o2 & n7; o2 |= n7;
            uint32_t ge2 = m2;

            // Bn <= 6 (at least 2 neighbors zero)
            uint32_t z, oz = ~n0, mz = 0;
            z = ~n1; mz |= oz & z; oz |= z;
            z = ~n2; mz |= oz & z; oz |= z;
            z = ~n3; mz |= oz & z; oz |= z;
            z = ~n4; mz |= oz & z; oz |= z;
            z = ~n5; mz |= oz & z; oz |= z;
            z = ~n6; mz |= oz & z; oz |= z;
            z = ~n7; mz |= oz & z; oz |= z;
            uint32_t le6 = mz;

            uint32_t cond = A1 & ge2 & le6;
            if (sub == 0)
                cond &= ~(n0 & n2 & n4) & ~(n2 & n4 & n6);
            else
                cond &= ~(n0 & n2 & n6) & ~(n0 & n4 & n6);

            removed |= cC & cond;
            nR[w] = cC & ~cond;

            aP = aC; aC = aN;
            cP = cC; cC = cN;
            bP = bC; bC = bN;
        }
        #pragma unroll
        for (int w = 0; w < 8; ++w) R[w] = nR[w];
        if (removed) {
            s_chg[s & 1][row] = s;
            s_changed = s;
            myLast = s;
        }
        (void)step;
    }

    // write out bit-packed skeleton from registers
    #pragma unroll
    for (int w = 0; w < 8; ++w)
        g_skel[m][b][row][wbase + w] = R[w];
}

// ---------------------------------------------------------------------------
// Kernel 2: dilation by Euclidean disk radius 3 + TP/FP/FN counting,
// fused finalize via ticket (integer counts -> deterministic).
// Grid (batch, slab): 16 x 16 blocks, 512 threads; 32 rows + 3-row halo.
// ---------------------------------------------------------------------------
#define SLAB 32
#define SROWS (SLAB + 6)
#define NBLK (BATCH * (Hn / SLAB))

__device__ __forceinline__ uint32_t hdil3s(const uint32_t* M, int r, int w) {
    uint32_t p = (w > 0)       ? M[r * WPR + w - 1] : 0u;
    uint32_t c =                 M[r * WPR + w];
    uint32_t n = (w < WPR - 1) ? M[r * WPR + w + 1] : 0u;
    uint32_t v = c;
    v |= (c >> 1) | (n << 31); v |= (c << 1) | (p >> 31);
    v |= (c >> 2) | (n << 30); v |= (c << 2) | (p >> 30);
    v |= (c >> 3) | (n << 29); v |= (c << 3) | (p >> 29);
    return v;
}
__device__ __forceinline__ uint32_t hdil2s(const uint32_t* M, int r, int w) {
    uint32_t p = (w > 0)       ? M[r * WPR + w - 1] : 0u;
    uint32_t c =                 M[r * WPR + w];
    uint32_t n = (w < WPR - 1) ? M[r * WPR + w + 1] : 0u;
    uint32_t v = c;
    v |= (c >> 1) | (n << 31); v |= (c << 1) | (p >> 31);
    v |= (c >> 2) | (n << 30); v |= (c << 2) | (p >> 30);
    return v;
}
__device__ __forceinline__ uint32_t dil3s(const uint32_t* M, int r, int w) {
    // squared radius 9: dy=0 -> |dx|<=3; |dy| in {1,2} -> |dx|<=2; |dy|=3 -> dx=0
    uint32_t v = hdil3s(M, r, w);
    v |= hdil2s(M, r - 1, w) | hdil2s(M, r + 1, w);
    v |= hdil2s(M, r - 2, w) | hdil2s(M, r + 2, w);
    v |= M[(r - 3) * WPR + w] | M[(r + 3) * WPR + w];
    return v;
}

__global__ void __launch_bounds__(512) count_kernel(float* __restrict__ out) {
    const int b    = blockIdx.x;
    const int slab = blockIdx.y;
    __shared__ uint32_t sP[SROWS * WPR];
    __shared__ uint32_t sG[SROWS * WPR];

    const uint32_t* P = &g_skel[0][b][0][0];
    const uint32_t* G = &g_skel[1][b][0][0];
    const int tid = threadIdx.x;
    const int base = slab * SLAB - 3;

    for (int i = tid; i < SROWS * WPR; i += 512) {
        int rr = base + i / WPR;
        int w  = i % WPR;
        uint32_t pv = 0, gv = 0;
        if (rr >= 0 && rr < Hn) { pv = P[rr * WPR + w]; gv = G[rr * WPR + w]; }
        sP[i] = pv; sG[i] = gv;
    }
    __syncthreads();

    const int rl = tid / WPR + 3;   // local row 3..34
    const int w  = tid % WPR;
    uint32_t dg = dil3s(sG, rl, w);
    uint32_t dp = dil3s(sP, rl, w);
    uint32_t pw = sP[rl * WPR + w];
    uint32_t gw = sG[rl * WPR + w];
    int tp = __popc(pw & dg);
    int fp = __popc(pw & ~dg);
    int fn = __popc(gw & ~dp);

    __shared__ int stp, sfp, sfn;
    if (tid == 0) { stp = 0; sfp = 0; sfn = 0; }
    __syncthreads();
    #pragma unroll
    for (int o = 16; o > 0; o >>= 1) {
        tp += __shfl_down_sync(0xffffffffu, tp, o);
        fp += __shfl_down_sync(0xffffffffu, fp, o);
        fn += __shfl_down_sync(0xffffffffu, fn, o);
    }
    if ((tid & 31) == 0) {
        atomicAdd(&stp, tp);
        atomicAdd(&sfp, fp);
        atomicAdd(&sfn, fn);
    }
    __syncthreads();

    __shared__ bool last;
    if (tid == 0) {
        atomicAdd(&g_counts[b][0], stp);
        atomicAdd(&g_counts[b][1], sfp);
        atomicAdd(&g_counts[b][2], sfn);
        __threadfence();
        int t = atomicAdd(&g_ticket, 1);
        last = (t == NBLK - 1);
    }
    __syncthreads();

    if (last && tid == 0) {
        float s0 = 0.f, s1 = 0.f, s2 = 0.f;
        for (int bb = 0; bb < BATCH; ++bb) {
            float TP = (float)g_counts[bb][0];
            float FP = (float)g_counts[bb][1];
            float FN = (float)g_counts[bb][2];
            s0 += TP / (TP + FP + 1e-12f);
            s1 += TP / (TP + FN + 1e-12f);
            s2 += TP / (TP + FP + FN + 1e-12f);
        }
        out[0] = s0 * (1.0f / BATCH);
        out[1] = s1 * (1.0f / BATCH);
        out[2] = s2 * (1.0f / BATCH);
    }
}

extern "C" void kernel_launch(void* const* d_in, const int* in_sizes, int n_in,
                              void* d_out, int out_size) {
    (void)in_sizes; (void)n_in; (void)out_size;
    const float* pred = (const float*)d_in[0];
    const float* gt   = (const float*)d_in[1];
    const int smem = 2 * BUFW * sizeof(uint32_t);   // ~69.6 KB
    cudaFuncSetAttribute(skel_kernel, cudaFuncAttributeMaxDynamicSharedMemorySize, smem);
    skel_kernel<<<32, 1024, smem>>>(pred, gt);
    count_kernel<<<dim3(BATCH, Hn / SLAB), 512>>>((float*)d_out);
}

// round 5
// speedup vs baseline: 3.7646x; 1.6753x over previous
#include <cuda_runtime.h>
#include <cstdint>

#define BATCH 16
#define Hn 512
#define Wn 512
#define WPR 16            // 32-bit words per row
#define ST 17             // smem row stride (bank padding)
#define CSIZE 4           // cluster size (CTAs per image)
#define CROWS (Hn / CSIZE)   // 128 rows per CTA
#define BR (CROWS + 2)       // rows incl. top/bottom halo
#define NTHR 512             // 4 threads per row

__device__ uint32_t g_skel[2][BATCH][Hn][WPR];
__device__ int g_counts[BATCH][3];   // TP, FP, FN (integer -> deterministic)
__device__ int g_ticket;

// ---------------------------------------------------------------------------
// helpers
// ---------------------------------------------------------------------------
__device__ __forceinline__ uint32_t smem_u32(const void* p) {
    uint32_t a;
    asm("{ .reg .u64 t; cvta.to.shared.u64 t, %1; cvt.u32.u64 %0, t; }"
        : "=r"(a) : "l"(p));
    return a;
}
__device__ __forceinline__ void st_cluster(uint32_t laddr, uint32_t rank, uint32_t val) {
    asm volatile(
        "{ .reg .b32 ra; mapa.shared::cluster.u32 ra, %0, %1; "
        "st.shared::cluster.u32 [ra], %2; }"
        :: "r"(laddr), "r"(rank), "r"(val) : "memory");
}
__device__ __forceinline__ uint32_t cluster_rank() {
    uint32_t r; asm("mov.u32 %0, %%cluster_ctarank;" : "=r"(r)); return r;
}
#define CLUSTER_SYNC() do { \
    asm volatile("barrier.cluster.arrive.aligned;" ::: "memory"); \
    asm volatile("barrier.cluster.wait.aligned;"   ::: "memory"); \
} while (0)

// ---------------------------------------------------------------------------
// Kernel 1: binarize + Zhang-Suen skeletonize to convergence.
// One 4-CTA cluster per (batch, mask) image; each CTA owns 128 rows.
// 512 threads: 4 per row, 4 words each, own words in registers.
// Ping-pong smem buffers; halo rows pushed to neighbors via DSMEM;
// ONE cluster barrier per sub-iteration. Dirty-row + skip-store tricks.
// ---------------------------------------------------------------------------
__global__ void __launch_bounds__(NTHR, 1) __cluster_dims__(CSIZE, 1, 1)
skel_kernel(const float* __restrict__ pred, const float* __restrict__ gt) {
    __shared__ uint32_t bufs[2][BR * ST];
    __shared__ int s_chg[2][BR];     // stamp of last change per row, by parity
    __shared__ int s_changed;        // local: max stamp with any removal
    __shared__ int c_changed;        // cluster: max stamp with any removal

    const int tid = threadIdx.x;
    const uint32_t rank = cluster_rank();
    const int img = blockIdx.x >> 2;
    const int b = img & 15;
    const int m = img >> 4;          // 0 = pred, 1 = gt
    const float* in = (m ? gt : pred) + (size_t)b * Hn * Wn + (size_t)rank * CROWS * Wn;

    // zero global counters + ticket (count kernel runs strictly after us)
    if (blockIdx.x == 0 && tid < BATCH * 3 + 1) {
        if (tid < BATCH * 3) (&g_counts[0][0])[tid] = 0;
        else g_ticket = 0;
    }

    // init stamps, flags, halo rows (halos stay 0 forever on image edges)
    if (tid < BR) { s_chg[0][tid] = 0; s_chg[1][tid] = 0; }
    if (tid == 0) { s_changed = 0; c_changed = 0; }
    if (tid < 2 * 2 * WPR) {          // 64 halo words: 2 bufs x {row 0, row BR-1}
        int bi = tid >> 5, r = (tid >> 4) & 1, w = tid & 15;
        bufs[bi][(r ? (BR - 1) : 0) * ST + w] = 0;
    }

    // --- binarize own 128 rows into bufs[0] (warp ballots -> packed words) ---
    #pragma unroll 4
    for (int p = 0; p < (CROWS * Wn) / NTHR; ++p) {
        int idx = p * NTHR + tid;
        float v = in[idx];
        uint32_t bits = __ballot_sync(0xffffffffu, v > 0.5f);
        if ((tid & 31) == 0) {
            int r = idx >> 9;            // local row
            int w = (idx >> 5) & 15;
            bufs[0][(r + 1) * ST + w] = bits;
        }
    }
    __syncthreads();

    const int lrow  = tid >> 2;          // 0..127
    const int q     = tid & 3;
    const int wbase = q * 4;
    const int i     = lrow + 1;          // buffer row index (1..128)
    const bool topB = (lrow == 0)        && (rank > 0);
    const bool botB = (lrow == CROWS-1)  && (rank < CSIZE - 1);

    uint32_t R[4];
    #pragma unroll
    for (int w = 0; w < 4; ++w) R[w] = bufs[0][i * ST + wbase + w];

    int s = 0;
    int myLast = 0;

    for (;;) {
        ++s;
        uint32_t* cur = bufs[s & 1];
        __syncthreads();                 // (A) order prior compute's smem writes

        // ---- store phase ----
        if (myLast > s - 3) {
            #pragma unroll
            for (int w = 0; w < 4; ++w) cur[i * ST + wbase + w] = R[w];
            if (topB) {
                #pragma unroll
                for (int w = 0; w < 4; ++w)
                    st_cluster(smem_u32(&cur[(BR - 1) * ST + wbase + w]), rank - 1, R[w]);
            }
            if (botB) {
                #pragma unroll
                for (int w = 0; w < 4; ++w)
                    st_cluster(smem_u32(&cur[0 * ST + wbase + w]), rank + 1, R[w]);
            }
        }
        // transmit own-row stamp of previous sub-iteration to neighbor halo
        if (q == 0) {
            const int pp = (s - 1) & 1;
            int stamp = s_chg[pp][i];
            if (topB) st_cluster(smem_u32(&s_chg[pp][BR - 1]), rank - 1, (uint32_t)stamp);
            if (botB) st_cluster(smem_u32(&s_chg[pp][0]),      rank + 1, (uint32_t)stamp);
        }
        // broadcast "changed at s-1" to all CTAs of the cluster
        if (tid == 0 && s_changed == s - 1) {
            uint32_t a = smem_u32(&c_changed);
            #pragma unroll
            for (int c = 0; c < CSIZE; ++c) st_cluster(a, c, (uint32_t)(s - 1));
        }
        CLUSTER_SYNC();                  // (B)

        if (c_changed <= s - 3) break;   // no removal in sub-iters s-1, s-2

        // ---- compute phase ----
        const int pb = (s - 1) & 1, ps = s - 1;
        bool dirty = (s_chg[pb][i] == ps) | (s_chg[pb][i - 1] == ps) | (s_chg[pb][i + 1] == ps);
        if (!dirty) continue;

        const int sub = (s + 1) & 1;     // s odd -> sub 0 ; s even -> sub 1
        const uint32_t* rU = &cur[(i - 1) * ST];
        const uint32_t* rO = &cur[i * ST];
        const uint32_t* rD = &cur[(i + 1) * ST];

        uint32_t aP = wbase ? rU[wbase - 1] : 0u;
        uint32_t cP = wbase ? rO[wbase - 1] : 0u;
        uint32_t bP = wbase ? rD[wbase - 1] : 0u;
        uint32_t aC = rU[wbase];
        uint32_t cC = R[0];
        uint32_t bC = rD[wbase];
        uint32_t cRight = (q < 3) ? rO[wbase + 4] : 0u;

        uint32_t removed = 0;
        uint32_t nR[4];
        #pragma unroll
        for (int w = 0; w < 4; ++w) {
            const int gw = wbase + w;
            uint32_t aN = 0, bN = 0, cN;
            if (gw < WPR - 1) { aN = rU[gw + 1]; bN = rD[gw + 1]; }
            cN = (w < 3) ? R[w + 1] : cRight;

            // P2..P9 clockwise from North
            uint32_t n0 = aC;
            uint32_t n1 = (aC >> 1) | (aN << 31);
            uint32_t n2 = (cC >> 1) | (cN << 31);
            uint32_t n3 = (bC >> 1) | (bN << 31);
            uint32_t n4 = bC;
            uint32_t n5 = (bC << 1) | (bP >> 31);
            uint32_t n6 = (cC << 1) | (cP >> 31);
            uint32_t n7 = (aC << 1) | (aP >> 31);

            // A == 1 (exactly one 0->1 transition around the ring)
            uint32_t e0 = ~n0 & n1, e1 = ~n1 & n2, e2 = ~n2 & n3, e3 = ~n3 & n4;
            uint32_t e4 = ~n4 & n5, e5 = ~n5 & n6, e6 = ~n6 & n7, e7 = ~n7 & n0;
            uint32_t one = e0, more = 0;
            more |= one & e1; one |= e1;
            more |= one & e2; one |= e2;
            more |= one & e3; one |= e3;
            more |= one & e4; one |= e4;
            more |= one & e5; one |= e5;
            more |= one & e6; one |= e6;
            more |= one & e7; one |= e7;
            uint32_t A1 = one & ~more;

            // Bn >= 2
            uint32_t o2 = n0, m2 = 0;
            m2 |= o2 & n1; o2 |= n1;
            m2 |= o2 & n2; o2 |= n2;
            m2 |= o2 & n3; o2 |= n3;
            m2 |= o2 & n4; o2 |= n4;
            m2 |= o2 & n5; o2 |= n5;
            m2 |= o2 & n6; o2 |= n6;
            m2 |= o2 & n7; o2 |= n7;
            uint32_t ge2 = m2;

            // Bn <= 6 (at least 2 neighbors zero)
            uint32_t z, oz = ~n0, mz = 0;
            z = ~n1; mz |= oz & z; oz |= z;
            z = ~n2; mz |= oz & z; oz |= z;
            z = ~n3; mz |= oz & z; oz |= z;
            z = ~n4; mz |= oz & z; oz |= z;
            z = ~n5; mz |= oz & z; oz |= z;
            z = ~n6; mz |= oz & z; oz |= z;
            z = ~n7; mz |= oz & z; oz |= z;
            uint32_t le6 = mz;

            uint32_t cond = A1 & ge2 & le6;
            if (sub == 0)
                cond &= ~(n0 & n2 & n4) & ~(n2 & n4 & n6);
            else
                cond &= ~(n0 & n2 & n6) & ~(n0 & n4 & n6);

            removed |= cC & cond;
            nR[w] = cC & ~cond;

            aP = aC; aC = aN;
            cP = cC; cC = cN;
            bP = bC; bC = bN;
        }
        #pragma unroll
        for (int w = 0; w < 4; ++w) R[w] = nR[w];
        if (removed) {
            s_chg[s & 1][i] = s;
            s_changed = s;
            myLast = s;
        }
    }

    // write out bit-packed skeleton from registers
    const int grow = (int)rank * CROWS + lrow;
    #pragma unroll
    for (int w = 0; w < 4; ++w)
        g_skel[m][b][grow][wbase + w] = R[w];
}

// ---------------------------------------------------------------------------
// Kernel 2: dilation by Euclidean disk radius 3 + TP/FP/FN counting,
// fused finalize via ticket (integer counts -> deterministic).
// Grid (batch, slab): 16 x 16 blocks, 512 threads; 32 rows + 3-row halo.
// ---------------------------------------------------------------------------
#define SLAB 32
#define SROWS (SLAB + 6)
#define NBLK (BATCH * (Hn / SLAB))

__device__ __forceinline__ uint32_t hdil3s(const uint32_t* M, int r, int w) {
    uint32_t p = (w > 0)       ? M[r * WPR + w - 1] : 0u;
    uint32_t c =                 M[r * WPR + w];
    uint32_t n = (w < WPR - 1) ? M[r * WPR + w + 1] : 0u;
    uint32_t v = c;
    v |= (c >> 1) | (n << 31); v |= (c << 1) | (p >> 31);
    v |= (c >> 2) | (n << 30); v |= (c << 2) | (p >> 30);
    v |= (c >> 3) | (n << 29); v |= (c << 3) | (p >> 29);
    return v;
}
__device__ __forceinline__ uint32_t hdil2s(const uint32_t* M, int r, int w) {
    uint32_t p = (w > 0)       ? M[r * WPR + w - 1] : 0u;
    uint32_t c =                 M[r * WPR + w];
    uint32_t n = (w < WPR - 1) ? M[r * WPR + w + 1] : 0u;
    uint32_t v = c;
    v |= (c >> 1) | (n << 31); v |= (c << 1) | (p >> 31);
    v |= (c >> 2) | (n << 30); v |= (c << 2) | (p >> 30);
    return v;
}
__device__ __forceinline__ uint32_t dil3s(const uint32_t* M, int r, int w) {
    // squared radius 9: dy=0 -> |dx|<=3; |dy| in {1,2} -> |dx|<=2; |dy|=3 -> dx=0
    uint32_t v = hdil3s(M, r, w);
    v |= hdil2s(M, r - 1, w) | hdil2s(M, r + 1, w);
    v |= hdil2s(M, r - 2, w) | hdil2s(M, r + 2, w);
    v |= M[(r - 3) * WPR + w] | M[(r + 3) * WPR + w];
    return v;
}

__global__ void __launch_bounds__(512) count_kernel(float* __restrict__ out) {
    const int b    = blockIdx.x;
    const int slab = blockIdx.y;
    __shared__ uint32_t sP[SROWS * WPR];
    __shared__ uint32_t sG[SROWS * WPR];

    const uint32_t* P = &g_skel[0][b][0][0];
    const uint32_t* G = &g_skel[1][b][0][0];
    const int tid = threadIdx.x;
    const int base = slab * SLAB - 3;

    for (int i = tid; i < SROWS * WPR; i += 512) {
        int rr = base + i / WPR;
        int w  = i % WPR;
        uint32_t pv = 0, gv = 0;
        if (rr >= 0 && rr < Hn) { pv = P[rr * WPR + w]; gv = G[rr * WPR + w]; }
        sP[i] = pv; sG[i] = gv;
    }
    __syncthreads();

    const int rl = tid / WPR + 3;   // local row 3..34
    const int w  = tid % WPR;
    uint32_t dg = dil3s(sG, rl, w);
    uint32_t dp = dil3s(sP, rl, w);
    uint32_t pw = sP[rl * WPR + w];
    uint32_t gw = sG[rl * WPR + w];
    int tp = __popc(pw & dg);
    int fp = __popc(pw & ~dg);
    int fn = __popc(gw & ~dp);

    __shared__ int stp, sfp, sfn;
    if (tid == 0) { stp = 0; sfp = 0; sfn = 0; }
    __syncthreads();
    #pragma unroll
    for (int o = 16; o > 0; o >>= 1) {
        tp += __shfl_down_sync(0xffffffffu, tp, o);
        fp += __shfl_down_sync(0xffffffffu, fp, o);
        fn += __shfl_down_sync(0xffffffffu, fn, o);
    }
    if ((tid & 31) == 0) {
        atomicAdd(&stp, tp);
        atomicAdd(&sfp, fp);
        atomicAdd(&sfn, fn);
    }
    __syncthreads();

    __shared__ bool last;
    if (tid == 0) {
        atomicAdd(&g_counts[b][0], stp);
        atomicAdd(&g_counts[b][1], sfp);
        atomicAdd(&g_counts[b][2], sfn);
        __threadfence();
        int t = atomicAdd(&g_ticket, 1);
        last = (t == NBLK - 1);
    }
    __syncthreads();

    if (last && tid == 0) {
        float s0 = 0.f, s1 = 0.f, s2 = 0.f;
        for (int bb = 0; bb < BATCH; ++bb) {
            float TP = (float)g_counts[bb][0];
            float FP = (float)g_counts[bb][1];
            float FN = (float)g_counts[bb][2];
            s0 += TP / (TP + FP + 1e-12f);
            s1 += TP / (TP + FN + 1e-12f);
            s2 += TP / (TP + FP + FN + 1e-12f);
        }
        out[0] = s0 * (1.0f / BATCH);
        out[1] = s1 * (1.0f / BATCH);
        out[2] = s2 * (1.0f / BATCH);
    }
}

extern "C" void kernel_launch(void* const* d_in, const int* in_sizes, int n_in,
                              void* d_out, int out_size) {
    (void)in_sizes; (void)n_in; (void)out_size;
    const float* pred = (const float*)d_in[0];
    const float* gt   = (const float*)d_in[1];
    skel_kernel<<<2 * BATCH * CSIZE, NTHR>>>(pred, gt);
    count_kernel<<<dim3(BATCH, Hn / SLAB), 512>>>((float*)d_out);
}